// round 5
// baseline (speedup 1.0000x reference)
#include <cuda_runtime.h>
#include <cstdint>

#define NL    8
#define NPOS  1024
#define DM    768
#define FT    4096
#define NPAIR 36
#define NT    512           // threads per GEMM CTA (16 warps, 4 per SMSP)

// ---------------------------------------------------------------------------
// Static device scratch
// ---------------------------------------------------------------------------
__device__ float g_xr  [(size_t)NL * NPOS * DM];        //  25 MB  rounded x
__device__ float g_wer [(size_t)NL * FT * DM];          // 100 MB  rounded W_enc
__device__ float g_wdr [(size_t)NPAIR * FT * DM];       // 453 MB  rounded triangular W_dec
__device__ float g_feats[(size_t)NL * NPOS * FT];       // 134 MB  feats (tf32-rounded)
__device__ float g_part[(size_t)NPAIR * NPOS * DM];     // 113 MB  decode partials

// ---------------------------------------------------------------------------
// Helpers
// ---------------------------------------------------------------------------
__device__ __forceinline__ unsigned f2tf(float x) {
    unsigned r;
    asm("cvt.rna.tf32.f32 %0, %1;" : "=r"(r) : "f"(x));
    return r;
}
__device__ __forceinline__ uint32_t smem_u32(const void* p) {
    uint32_t a;
    asm("{ .reg .u64 t; cvta.to.shared.u64 t, %1; cvt.u32.u64 %0, t; }" : "=r"(a) : "l"(p));
    return a;
}
#define CP_ASYNC16(dst, src) \
    asm volatile("cp.async.cg.shared.global [%0], [%1], 16;" :: "r"(dst), "l"(src))
#define CP_COMMIT() asm volatile("cp.async.commit_group;" ::: "memory")
#define CP_WAIT2()  asm volatile("cp.async.wait_group 2;" ::: "memory")

__device__ __forceinline__ void mma_tf32(float c[4],
                                         unsigned a0, unsigned a1, unsigned a2, unsigned a3,
                                         unsigned b0, unsigned b1) {
    asm volatile(
        "mma.sync.aligned.m16n8k8.row.col.f32.tf32.tf32.f32 "
        "{%0,%1,%2,%3}, {%4,%5,%6,%7}, {%8,%9}, {%0,%1,%2,%3};"
        : "+f"(c[0]), "+f"(c[1]), "+f"(c[2]), "+f"(c[3])
        : "r"(a0), "r"(a1), "r"(a2), "r"(a3), "r"(b0), "r"(b1));
}

// ---------------------------------------------------------------------------
// SMEM: 4 stages; A tile 256x32 (stride 36 floats)
//   decode B: 32 x 128 (stride 136 floats); encode B: 128 x 32 (stride 36)
// ---------------------------------------------------------------------------
#define STAGES 4
#define ASTR  36
#define BKSTR 136
#define A_BYTES (256 * ASTR * 4)         // 36864
#define B_OFF   A_BYTES
#define B_BYTES (128 * ASTR * 4)         // 18432 >= 32*136*4
#define STAGE   (A_BYTES + B_BYTES)      // 55296
#define SMEM_BYTES (STAGES * STAGE)      // 221184

__device__ __forceinline__ void loadA(const float* __restrict__ src, size_t gstr,
                                      uint32_t dst, int tid) {
#pragma unroll
    for (int q = 0; q < 4; q++) {
        int idx = tid + q * NT;
        int row = idx >> 3, seg = idx & 7;
        CP_ASYNC16(dst + (row * ASTR + seg * 4) * 4, src + (size_t)row * gstr + seg * 4);
    }
}
__device__ __forceinline__ void loadB_kn(const float* __restrict__ src, size_t gstr,
                                         uint32_t dst, int tid) {
#pragma unroll
    for (int q = 0; q < 2; q++) {
        int idx = tid + q * NT;
        int row = idx >> 5, seg = idx & 31;
        CP_ASYNC16(dst + (row * BKSTR + seg * 4) * 4, src + (size_t)row * gstr + seg * 4);
    }
}
__device__ __forceinline__ void loadB_nk(const float* __restrict__ src, size_t gstr,
                                         uint32_t dst, int tid) {
#pragma unroll
    for (int q = 0; q < 2; q++) {
        int idx = tid + q * NT;
        int row = idx >> 3, seg = idx & 7;
        CP_ASYNC16(dst + (row * ASTR + seg * 4) * 4, src + (size_t)row * gstr + seg * 4);
    }
}

// compute one K=32 chunk. Warp tile 64(M) x 32(N): mf=4, nf=4.
// B_KN=1: Bs[k][n] (decode); B_KN=0: Bs[n][k] (encode)
template <int B_KN>
__device__ __forceinline__ void compute_chunk(const float* __restrict__ smem, int stage,
                                              int wm, int wn, int lane,
                                              float acc[4][4][4]) {
    const unsigned* As = (const unsigned*)(smem) + stage * (STAGE / 4);
    const unsigned* Bs = As + A_BYTES / 4;
#pragma unroll
    for (int kk = 0; kk < 4; kk++) {
        const int kb = kk * 8;
        unsigned a[4][4], b[4][2];
#pragma unroll
        for (int mf = 0; mf < 4; mf++) {
            int r0 = wm * 64 + mf * 16 + (lane >> 2);
            int kc = kb + (lane & 3);
            a[mf][0] = As[r0 * ASTR + kc];
            a[mf][1] = As[(r0 + 8) * ASTR + kc];
            a[mf][2] = As[r0 * ASTR + kc + 4];
            a[mf][3] = As[(r0 + 8) * ASTR + kc + 4];
        }
#pragma unroll
        for (int nf = 0; nf < 4; nf++) {
            int n = wn * 32 + nf * 8 + (lane >> 2);
            int kc = kb + (lane & 3);
            if (B_KN) {
                b[nf][0] = Bs[kc * BKSTR + n];
                b[nf][1] = Bs[(kc + 4) * BKSTR + n];
            } else {
                b[nf][0] = Bs[n * ASTR + kc];
                b[nf][1] = Bs[n * ASTR + kc + 4];
            }
        }
#pragma unroll
        for (int mf = 0; mf < 4; mf++)
#pragma unroll
            for (int nf = 0; nf < 4; nf++)
                mma_tf32(acc[mf][nf], a[mf][0], a[mf][1], a[mf][2], a[mf][3],
                         b[nf][0], b[nf][1]);
    }
}

// ---------------------------------------------------------------------------
// Prep kernels
// ---------------------------------------------------------------------------
__global__ void round_copy(const float* __restrict__ src, float* __restrict__ dst) {
    size_t i = ((size_t)blockIdx.x * 256 + threadIdx.x) * 4;
    float4 v = *(const float4*)(src + i);
    uint4 o = { f2tf(v.x), f2tf(v.y), f2tf(v.z), f2tf(v.w) };
    *(uint4*)(dst + i) = o;
}
__global__ void round_wdec(const float* __restrict__ W_dec) {
    int p = blockIdx.y;
    int j = 0, a = 0;
    while (a + j + 1 <= p) { a += j + 1; ++j; }
    int i = p - a;
    const float* src = W_dec + (size_t)(i * NL + j) * FT * DM;
    float* dst = g_wdr + (size_t)p * FT * DM;
    size_t e = ((size_t)blockIdx.x * 256 + threadIdx.x) * 4;
    float4 v = *(const float4*)(src + e);
    uint4 o = { f2tf(v.x), f2tf(v.y), f2tf(v.z), f2tf(v.w) };
    *(uint4*)(dst + e) = o;
}

// ---------------------------------------------------------------------------
// Encoder: feats = relu(x @ W_enc^T + b_enc). grid (FT/128, NPOS/256, NL)
// ---------------------------------------------------------------------------
__global__ __launch_bounds__(NT, 1)
void encode_tc(const float* __restrict__ b_enc) {
    extern __shared__ float smem[];
    const int l = blockIdx.z, m0 = blockIdx.y * 256, n0 = blockIdx.x * 128;
    const int tid = threadIdx.x, lane = tid & 31, warp = tid >> 5;
    const int wm = warp & 3, wn = warp >> 2;   // 4 x 4 warp grid
    const uint32_t sb = smem_u32(smem);

    float acc[4][4][4];
#pragma unroll
    for (int a = 0; a < 4; a++)
#pragma unroll
        for (int b = 0; b < 4; b++)
#pragma unroll
            for (int c = 0; c < 4; c++) acc[a][b][c] = 0.f;

    const float* abase = g_xr  + ((size_t)l * NPOS + m0) * DM;
    const float* bbase = g_wer + ((size_t)l * FT + n0) * DM;
    const int NC = DM / 32;

#pragma unroll
    for (int s = 0; s < STAGES - 1; s++) {
        loadA(abase + s * 32, DM, sb + s * STAGE, tid);
        loadB_nk(bbase + s * 32, DM, sb + s * STAGE + B_OFF, tid);
        CP_COMMIT();
    }
    for (int c = 0; c < NC; c++) {
        CP_WAIT2();
        __syncthreads();
        int nc = c + STAGES - 1;
        if (nc < NC) {
            uint32_t s = sb + (nc & 3) * STAGE;
            loadA(abase + nc * 32, DM, s, tid);
            loadB_nk(bbase + nc * 32, DM, s + B_OFF, tid);
        }
        CP_COMMIT();
        compute_chunk<0>(smem, c & 3, wm, wn, lane, acc);
    }

    // epilogue: bias + relu + tf32 round -> g_feats
    const float* be = b_enc + (size_t)l * FT + n0;
#pragma unroll
    for (int mf = 0; mf < 4; mf++) {
        int r0 = m0 + wm * 64 + mf * 16 + (lane >> 2);
        float* d0 = g_feats + ((size_t)l * NPOS + r0) * FT + n0;
        float* d1 = d0 + 8 * FT;
#pragma unroll
        for (int nf = 0; nf < 4; nf++) {
            int c0 = wn * 32 + nf * 8 + (lane & 3) * 2;
            float b0 = be[c0], b1 = be[c0 + 1];
            uint2 v0 = { f2tf(fmaxf(acc[mf][nf][0] + b0, 0.f)),
                         f2tf(fmaxf(acc[mf][nf][1] + b1, 0.f)) };
            uint2 v1 = { f2tf(fmaxf(acc[mf][nf][2] + b0, 0.f)),
                         f2tf(fmaxf(acc[mf][nf][3] + b1, 0.f)) };
            *(uint2*)(d0 + c0) = v0;
            *(uint2*)(d1 + c0) = v1;
        }
    }
}

// ---------------------------------------------------------------------------
// Decoder partials: g_part[p] = feats[i] @ W_dec[i,j]. grid (DM/128, NPOS/256, NPAIR)
// ---------------------------------------------------------------------------
__global__ __launch_bounds__(NT, 1)
void decode_tc() {
    extern __shared__ float smem[];
    const int p = blockIdx.z, m0 = blockIdx.y * 256, n0 = blockIdx.x * 128;
    int j = 0, a0 = 0;
    while (a0 + j + 1 <= p) { a0 += j + 1; ++j; }
    const int i = p - a0;
    const int tid = threadIdx.x, lane = tid & 31, warp = tid >> 5;
    const int wm = warp & 3, wn = warp >> 2;
    const uint32_t sb = smem_u32(smem);

    float acc[4][4][4];
#pragma unroll
    for (int a = 0; a < 4; a++)
#pragma unroll
        for (int b = 0; b < 4; b++)
#pragma unroll
            for (int c = 0; c < 4; c++) acc[a][b][c] = 0.f;

    const float* abase = g_feats + ((size_t)i * NPOS + m0) * FT;
    const float* bbase = g_wdr + (size_t)p * FT * DM + n0;
    const int NC = FT / 32;

#pragma unroll
    for (int s = 0; s < STAGES - 1; s++) {
        loadA(abase + s * 32, FT, sb + s * STAGE, tid);
        loadB_kn(bbase + (size_t)s * 32 * DM, DM, sb + s * STAGE + B_OFF, tid);
        CP_COMMIT();
    }
    for (int c = 0; c < NC; c++) {
        CP_WAIT2();
        __syncthreads();
        int nc = c + STAGES - 1;
        if (nc < NC) {
            uint32_t s = sb + (nc & 3) * STAGE;
            loadA(abase + nc * 32, FT, s, tid);
            loadB_kn(bbase + (size_t)nc * 32 * DM, DM, s + B_OFF, tid);
        }
        CP_COMMIT();
        compute_chunk<1>(smem, c & 3, wm, wn, lane, acc);
    }

    // epilogue -> g_part
#pragma unroll
    for (int mf = 0; mf < 4; mf++) {
        int r0 = m0 + wm * 64 + mf * 16 + (lane >> 2);
        float* d0 = g_part + ((size_t)p * NPOS + r0) * DM + n0;
        float* d1 = d0 + 8 * DM;
#pragma unroll
        for (int nf = 0; nf < 4; nf++) {
            int c0 = wn * 32 + nf * 8 + (lane & 3) * 2;
            float2 v0 = { acc[mf][nf][0], acc[mf][nf][1] };
            float2 v1 = { acc[mf][nf][2], acc[mf][nf][3] };
            *(float2*)(d0 + c0) = v0;
            *(float2*)(d1 + c0) = v1;
        }
    }
}

// ---------------------------------------------------------------------------
// Fixed-order reduction over sources + bias. grid (NPOS*DM/1024, NL)
// ---------------------------------------------------------------------------
__global__ __launch_bounds__(256, 4)
void reduce_out(const float* __restrict__ b_dec, float* __restrict__ out) {
    const int jj = blockIdx.y;
    const int base = jj * (jj + 1) / 2;
    size_t lin = ((size_t)blockIdx.x * 256 + threadIdx.x) * 4;
    int d = (int)(lin % DM);
    float4 acc = *(const float4*)(b_dec + (size_t)jj * DM + d);
    for (int i = 0; i <= jj; i++) {
        float4 v = *(const float4*)(g_part + (size_t)(base + i) * NPOS * DM + lin);
        acc.x += v.x; acc.y += v.y; acc.z += v.z; acc.w += v.w;
    }
    *(float4*)(out + (size_t)jj * NPOS * DM + lin) = acc;
}

// ---------------------------------------------------------------------------
extern "C" void kernel_launch(void* const* d_in, const int* in_sizes, int n_in,
                              void* d_out, int out_size) {
    const float* x     = (const float*)d_in[0];
    const float* W_enc = (const float*)d_in[1];
    const float* b_enc = (const float*)d_in[2];
    const float* W_dec = (const float*)d_in[3];
    const float* b_dec = (const float*)d_in[4];
    float* out = (float*)d_out;

    static cudaStream_t s2 = nullptr;
    static cudaEvent_t evA = nullptr, evB = nullptr;
    if (!s2) {
        cudaFuncSetAttribute(encode_tc, cudaFuncAttributeMaxDynamicSharedMemorySize, SMEM_BYTES);
        cudaFuncSetAttribute(decode_tc, cudaFuncAttributeMaxDynamicSharedMemorySize, SMEM_BYTES);
        cudaStreamCreateWithFlags(&s2, cudaStreamNonBlocking);
        cudaEventCreateWithFlags(&evA, cudaEventDisableTiming);
        cudaEventCreateWithFlags(&evB, cudaEventDisableTiming);
    }

    float* g_xr_p;   cudaGetSymbolAddress((void**)&g_xr_p,  g_xr);
    float* g_wer_p;  cudaGetSymbolAddress((void**)&g_wer_p, g_wer);

    // Fork: W_dec rounding on side stream, overlapped with encode chain.
    cudaEventRecord(evA, 0);
    cudaStreamWaitEvent(s2, evA, 0);
    round_wdec<<<dim3((FT * DM) / 1024, NPAIR), 256, 0, s2>>>(W_dec);
    cudaEventRecord(evB, s2);

    round_copy<<<(NL * NPOS * DM) / 1024, 256>>>(x, g_xr_p);
    round_copy<<<(NL * FT * DM) / 1024, 256>>>(W_enc, g_wer_p);
    encode_tc<<<dim3(FT / 128, NPOS / 256, NL), NT, SMEM_BYTES>>>(b_enc);

    // Join, then decode + reduce.
    cudaStreamWaitEvent(0, evB, 0);
    decode_tc<<<dim3(DM / 128, NPOS / 256, NPAIR), NT, SMEM_BYTES>>>();
    reduce_out<<<dim3(NPOS * DM / 1024, NL), 256>>>(b_dec, out);
}